// round 14
// baseline (speedup 1.0000x reference)
#include <cuda_runtime.h>
#include <cstdint>
#include <cstddef>

#define BDIM 8192
#define CDIM 256
#define NITER 100
#define NBLKMAX 1024
#define NQUAD (BDIM / 4)    // 2048 row-quads
#define NSEG 16
#define L2E 1.4426950408889634f
#define LN2 0.69314718055994531f

// Scratch: __device__ globals (no cudaMalloc allowed)
__device__ __align__(256) float g_M [(size_t)BDIM * BDIM];      // M[i][j] = 2*x_i.y_j
__device__ __align__(256) float g_b[BDIM];
__device__ __align__(256) float g_colm[(size_t)NBLKMAX * BDIM]; // per-block col max partial
__device__ __align__(256) float g_cols[(size_t)NBLKMAX * BDIM]; // per-block col sum partial

__device__ __forceinline__ float ex2f(float x) {
    float y; asm("ex2.approx.f32 %0, %1;" : "=f"(y) : "f"(x)); return y;
}
__device__ __forceinline__ float lg2f(float x) {
    float y; asm("lg2.approx.f32 %0, %1;" : "=f"(y) : "f"(x)); return y;
}

// ---------------------------------------------------------------------------
// b init: b[j] = -||y_j||^2   (one warp per row, 8 rows per block)
// ---------------------------------------------------------------------------
__global__ __launch_bounds__(256) void init_b_kernel(const float* __restrict__ Y)
{
    int warp = threadIdx.x >> 5, lane = threadIdx.x & 31;
    int row = (blockIdx.x << 3) + warp;
    const float4* yr = (const float4*)Y + (size_t)row * (CDIM / 4);
    float4 v0 = yr[lane];
    float4 v1 = yr[lane + 32];
    float ss = 0.f;
    ss = fmaf(v0.x, v0.x, ss); ss = fmaf(v0.y, v0.y, ss);
    ss = fmaf(v0.z, v0.z, ss); ss = fmaf(v0.w, v0.w, ss);
    ss = fmaf(v1.x, v1.x, ss); ss = fmaf(v1.y, v1.y, ss);
    ss = fmaf(v1.z, v1.z, ss); ss = fmaf(v1.w, v1.w, ss);
    #pragma unroll
    for (int off = 16; off; off >>= 1)
        ss += __shfl_xor_sync(0xffffffffu, ss, off);
    if (lane == 0) g_b[row] = -ss;
}

// ---------------------------------------------------------------------------
// GEMM: M = 2 * X * Y^T (row-major only).
// ---------------------------------------------------------------------------
__global__ __launch_bounds__(256) void gemm_kernel(const float* __restrict__ X,
                                                   const float* __restrict__ Y)
{
    __shared__ float As[16][128];
    __shared__ float Bs[16][128];

    const int tid = threadIdx.x;
    const int tx = tid & 15;
    const int ty = tid >> 4;
    const int i0 = blockIdx.y << 7;
    const int j0 = blockIdx.x << 7;

    const float4* X4 = (const float4*)X;
    const float4* Y4 = (const float4*)Y;

    float acc[8][8];
    #pragma unroll
    for (int r = 0; r < 8; r++)
        #pragma unroll
        for (int c = 0; c < 8; c++) acc[r][c] = 0.f;

    for (int k0 = 0; k0 < CDIM; k0 += 16) {
        #pragma unroll
        for (int p = 0; p < 2; p++) {
            int f = tid + (p << 8);
            int r = f >> 2;
            int q = f & 3;
            float4 a = X4[(size_t)(i0 + r) * (CDIM / 4) + (k0 >> 2) + q];
            As[q * 4 + 0][r] = a.x; As[q * 4 + 1][r] = a.y;
            As[q * 4 + 2][r] = a.z; As[q * 4 + 3][r] = a.w;
            float4 b = Y4[(size_t)(j0 + r) * (CDIM / 4) + (k0 >> 2) + q];
            Bs[q * 4 + 0][r] = b.x; Bs[q * 4 + 1][r] = b.y;
            Bs[q * 4 + 2][r] = b.z; Bs[q * 4 + 3][r] = b.w;
        }
        __syncthreads();
        #pragma unroll
        for (int kk = 0; kk < 16; kk++) {
            float af[8], bf[8];
            *(float4*)&af[0] = *(const float4*)&As[kk][ty * 8];
            *(float4*)&af[4] = *(const float4*)&As[kk][ty * 8 + 4];
            *(float4*)&bf[0] = *(const float4*)&Bs[kk][tx * 8];
            *(float4*)&bf[4] = *(const float4*)&Bs[kk][tx * 8 + 4];
            #pragma unroll
            for (int r = 0; r < 8; r++)
                #pragma unroll
                for (int c = 0; c < 8; c++)
                    acc[r][c] = fmaf(af[r], bf[c], acc[r][c]);
        }
        __syncthreads();
    }

    #pragma unroll
    for (int r = 0; r < 8; r++) {
        int i = i0 + ty * 8 + r;
        float4 w0 = make_float4(2.f * acc[r][0], 2.f * acc[r][1],
                                2.f * acc[r][2], 2.f * acc[r][3]);
        float4 w1 = make_float4(2.f * acc[r][4], 2.f * acc[r][5],
                                2.f * acc[r][6], 2.f * acc[r][7]);
        float4* dst = (float4*)(g_M + (size_t)i * BDIM + j0 + tx * 8);
        dst[0] = w0; dst[1] = w1;
    }
}

// ---------------------------------------------------------------------------
// Fused Sinkhorn iteration, batched two-sub-phase schedule.
// Block ranges are QUAD-ALIGNED: every block owns whole 4-row batches, so
// all warps execute identical control flow (full-mask shuffles are safe).
// Per 4-row batch:
//   Phase A: stream 4 rows from DRAM (ldg -> lines stay L2-resident),
//            double-buffered, stripe (m,s) -> smem; barrier;
//            2-warp combine -> a[0..3]; barrier.
//   Phase B: re-read the 4 rows from L2 (ldcs, last touch), col-update with
//            col state held in registers for the whole batch.
// Warp w owns column stripe [512w, 512w+512). Col state stripe-private.
// ---------------------------------------------------------------------------
__global__ __launch_bounds__(512, 2) void fused_iter_kernel(const float* __restrict__ Mmat,
                                                            const float* __restrict__ bsrc,
                                                            float* __restrict__ colm,
                                                            float* __restrict__ cols)
{
    extern __shared__ float dsm[];
    float* sb = dsm;               // 8192: staged b
    float* cm = dsm + 8192;        // 8192: per-col running max
    float* cs = dsm + 16384;       // 8192: per-col running sum
    float* pm = dsm + 24576;       // 64: stripe maxes (4 rows x 16)
    float* ps = pm + 64;           // 64: stripe sums
    float* sa = ps + 64;           // 4: a[0..3]

    const int tid = threadIdx.x;
    const int lane = tid & 31, warp = tid >> 5;
    const int nblk = gridDim.x;
    const int q0 = (int)(((long long)NQUAD * blockIdx.x) / nblk);
    const int q1 = (int)(((long long)NQUAD * (blockIdx.x + 1)) / nblk);
    const int r0 = q0 << 2, r1 = q1 << 2;    // quad-aligned row range

    // stage b
    float4* sb4 = (float4*)sb;
    const float4* s4 = (const float4*)bsrc;
    #pragma unroll
    for (int k = 0; k < 4; k++) sb4[tid + 512 * k] = s4[tid + 512 * k];

    // init stripe-private col state
    float4* cm4 = (float4*)cm;
    float4* cs4 = (float4*)cs;
    const int sbase = warp * 128 + lane;      // float4 index within row
    #pragma unroll
    for (int u = 0; u < 4; u++) {
        cm4[sbase + 32 * u] = make_float4(-3.0e38f, -3.0e38f, -3.0e38f, -3.0e38f);
        cs4[sbase + 32 * u] = make_float4(0.f, 0.f, 0.f, 0.f);
    }
    __syncthreads();

    const float4* Mb = (const float4*)Mmat;

    for (int r = r0; r < r1; r += 4) {
        // ---- Phase A: row stats, double-buffered DRAM stream ----
        float4 cur[4], nxt[4];
        #pragma unroll
        for (int u = 0; u < 4; u++)
            cur[u] = __ldg(Mb + ((size_t)r << 11) + sbase + 32 * u);

        #pragma unroll
        for (int b = 0; b < 4; b++) {
            if (b < 3) {
                #pragma unroll
                for (int u = 0; u < 4; u++)
                    nxt[u] = __ldg(Mb + ((size_t)(r + b + 1) << 11) + sbase + 32 * u);
            }
            #pragma unroll
            for (int u = 0; u < 4; u++) {
                float4 bb = sb4[sbase + 32 * u];
                cur[u].x += bb.x; cur[u].y += bb.y;
                cur[u].z += bb.z; cur[u].w += bb.w;
            }
            float m = -3.0e38f;
            #pragma unroll
            for (int u = 0; u < 4; u++)
                m = fmaxf(m, fmaxf(fmaxf(cur[u].x, cur[u].y), fmaxf(cur[u].z, cur[u].w)));
            #pragma unroll
            for (int off = 16; off; off >>= 1)
                m = fmaxf(m, __shfl_xor_sync(0xffffffffu, m, off));
            const float mk = m * L2E;
            float s = 0.f;
            #pragma unroll
            for (int u = 0; u < 4; u++) {
                s += ex2f(fmaf(cur[u].x, L2E, -mk));
                s += ex2f(fmaf(cur[u].y, L2E, -mk));
                s += ex2f(fmaf(cur[u].z, L2E, -mk));
                s += ex2f(fmaf(cur[u].w, L2E, -mk));
            }
            #pragma unroll
            for (int off = 16; off; off >>= 1)
                s += __shfl_xor_sync(0xffffffffu, s, off);
            if (lane == 0) { pm[b * 16 + warp] = m; ps[b * 16 + warp] = s; }
            #pragma unroll
            for (int u = 0; u < 4; u++) cur[u] = nxt[u];
        }
        __syncthreads();

        // ---- combine: warps 0-1, 16 lanes per row (always 4 rows: no
        //      divergence, full-mask shuffles safe) ----
        if (warp < 2) {
            const int row_b = warp * 2 + (lane >> 4);   // 0..3, always valid
            const int stripe = lane & 15;
            float m = pm[row_b * 16 + stripe];
            float s = ps[row_b * 16 + stripe];
            float mm = m;
            #pragma unroll
            for (int off = 1; off <= 8; off <<= 1)
                mm = fmaxf(mm, __shfl_xor_sync(0xffffffffu, mm, off));
            float t = s * ex2f((m - mm) * L2E);
            #pragma unroll
            for (int off = 1; off <= 8; off <<= 1)
                t += __shfl_xor_sync(0xffffffffu, t, off);
            if ((lane & 15) == 0) sa[row_b] = -(mm + lg2f(t) * LN2);
        }
        __syncthreads();

        // ---- Phase B: L2 re-read + col update, col state in registers ----
        float4 cmv[4], csv[4];
        #pragma unroll
        for (int u = 0; u < 4; u++) {
            cmv[u] = cm4[sbase + 32 * u];
            csv[u] = cs4[sbase + 32 * u];
        }
        #pragma unroll
        for (int b = 0; b < 4; b++) {
            const float ab = sa[b];
            #pragma unroll
            for (int u = 0; u < 4; u++) {
                float4 mmv = __ldcs(Mb + ((size_t)(r + b) << 11) + sbase + 32 * u);
                float4 bb = sb4[sbase + 32 * u];
                #define COLUPD(C)                                               \
                {                                                               \
                    float c = mmv.C + bb.C + ab;                                \
                    if (c <= cmv[u].C) {                                        \
                        csv[u].C += ex2f((c - cmv[u].C) * L2E);                 \
                    } else {                                                    \
                        csv[u].C = csv[u].C * ex2f((cmv[u].C - c) * L2E) + 1.0f;\
                        cmv[u].C = c;                                           \
                    }                                                           \
                }
                COLUPD(x) COLUPD(y) COLUPD(z) COLUPD(w)
                #undef COLUPD
            }
        }
        #pragma unroll
        for (int u = 0; u < 4; u++) {
            cm4[sbase + 32 * u] = cmv[u];
            cs4[sbase + 32 * u] = csv[u];
        }
        // next batch's Phase-A barrier guards sa/pm/ps reuse
    }
    __syncthreads();

    // write block partials (coalesced)
    float* cmo = colm + (size_t)blockIdx.x * BDIM;
    float* cso = cols + (size_t)blockIdx.x * BDIM;
    #pragma unroll
    for (int k = 0; k < 16; k++) {
        int j = tid + 512 * k;
        cmo[j] = cm[j];
        cso[j] = cs[j];
    }
}

// ---------------------------------------------------------------------------
// Hierarchical combine: 16 segments/column, 2 interleaved online sub-chains
// per segment. Fixed order everywhere -> deterministic.
// Grid 256 x 512 threads: lane -> column within 32-col group, warp -> segment.
// ---------------------------------------------------------------------------
__global__ __launch_bounds__(512) void reduce_b_kernel(const float* __restrict__ colm,
                                                       const float* __restrict__ cols,
                                                       float* __restrict__ b, int nblk)
{
    __shared__ float sm_m[NSEG][32];
    __shared__ float sm_s[NSEG][32];
    const int lane32 = threadIdx.x & 31;
    const int seg = threadIdx.x >> 5;
    const int j = blockIdx.x * 32 + lane32;
    const int k0 = seg * nblk / NSEG;
    const int k1 = (seg + 1) * nblk / NSEG;

    float m0 = -3.0e38f, s0 = 0.f;
    float m1 = -3.0e38f, s1 = 0.f;
    int k = k0;
    for (; k + 1 < k1; k += 2) {
        float am = colm[(size_t)k * BDIM + j];
        float as = cols[(size_t)k * BDIM + j];
        float bm = colm[(size_t)(k + 1) * BDIM + j];
        float bs = cols[(size_t)(k + 1) * BDIM + j];
        if (am <= m0) { s0 += as * ex2f((am - m0) * L2E); }
        else          { s0 = s0 * ex2f((m0 - am) * L2E) + as; m0 = am; }
        if (bm <= m1) { s1 += bs * ex2f((bm - m1) * L2E); }
        else          { s1 = s1 * ex2f((m1 - bm) * L2E) + bs; m1 = bm; }
    }
    if (k < k1) {
        float am = colm[(size_t)k * BDIM + j];
        float as = cols[(size_t)k * BDIM + j];
        if (am <= m0) { s0 += as * ex2f((am - m0) * L2E); }
        else          { s0 = s0 * ex2f((m0 - am) * L2E) + as; m0 = am; }
    }
    float m = fmaxf(m0, m1);
    float s = s0 * ex2f((m0 - m) * L2E) + s1 * ex2f((m1 - m) * L2E);
    sm_m[seg][lane32] = m;
    sm_s[seg][lane32] = s;
    __syncthreads();

    if (threadIdx.x < 32) {
        float mm = sm_m[0][lane32], ss = sm_s[0][lane32];
        #pragma unroll
        for (int q = 1; q < NSEG; q++) {
            float bm = sm_m[q][lane32], bs = sm_s[q][lane32];
            if (bm <= mm) { ss += bs * ex2f((bm - mm) * L2E); }
            else          { ss = ss * ex2f((mm - bm) * L2E) + bs; mm = bm; }
        }
        b[j] = b[j] - (mm + lg2f(ss) * LN2);
    }
}

// ---------------------------------------------------------------------------
// Final: out[i][:] = y[ argmax_j (M[i][j] + b[j]) ][:]
// ---------------------------------------------------------------------------
__global__ __launch_bounds__(256) void argmax_gather_kernel(const float* __restrict__ Y,
                                                            float* __restrict__ out)
{
    __shared__ float sb[BDIM];
    __shared__ float sval[8];
    __shared__ int   sidx[8];
    __shared__ int   sjbest;
    const int tid = threadIdx.x;
    const int lane = tid & 31, warp = tid >> 5;

    float4* sb4 = (float4*)sb;
    const float4* s4 = (const float4*)g_b;
    #pragma unroll
    for (int k = 0; k < 8; k++) sb4[tid + 256 * k] = s4[tid + 256 * k];
    __syncthreads();

    const int row0 = blockIdx.x << 3;
    for (int rr = 0; rr < 8; rr++) {
        const int row = row0 + rr;
        const float4* m4 = (const float4*)(g_M + (size_t)row * BDIM);

        float best = -3.0e38f;
        int bidx = 0x7fffffff;
        #pragma unroll
        for (int k = 0; k < 8; k++) {
            int f = tid + 256 * k;
            float4 m = __ldcs(m4 + f);
            float4 bb = sb4[f];
            float vx = m.x + bb.x, vy = m.y + bb.y, vz = m.z + bb.z, vw = m.w + bb.w;
            int j = f * 4;
            if (vx > best || (vx == best && j     < bidx)) { best = vx; bidx = j; }
            if (vy > best || (vy == best && j + 1 < bidx)) { best = vy; bidx = j + 1; }
            if (vz > best || (vz == best && j + 2 < bidx)) { best = vz; bidx = j + 2; }
            if (vw > best || (vw == best && j + 3 < bidx)) { best = vw; bidx = j + 3; }
        }
        #pragma unroll
        for (int off = 16; off; off >>= 1) {
            float ov = __shfl_xor_sync(0xffffffffu, best, off);
            int   oi = __shfl_xor_sync(0xffffffffu, bidx, off);
            if (ov > best || (ov == best && oi < bidx)) { best = ov; bidx = oi; }
        }
        if (lane == 0) { sval[warp] = best; sidx[warp] = bidx; }
        __syncthreads();
        if (tid == 0) {
            float bv = sval[0]; int bj = sidx[0];
            #pragma unroll
            for (int w = 1; w < 8; w++) {
                if (sval[w] > bv || (sval[w] == bv && sidx[w] < bj)) {
                    bv = sval[w]; bj = sidx[w];
                }
            }
            sjbest = bj;
        }
        __syncthreads();
        out[(size_t)row * CDIM + tid] = Y[(size_t)sjbest * CDIM + tid];
        __syncthreads();
    }
}

// ---------------------------------------------------------------------------
extern "C" void kernel_launch(void* const* d_in, const int* in_sizes, int n_in,
                              void* d_out, int out_size)
{
    const float* X = (const float*)d_in[0];
    const float* Y = (const float*)d_in[1];
    float* out = (float*)d_out;

    float *Mp, *bp, *cmp, *csp;
    cudaGetSymbolAddress((void**)&Mp,  g_M);
    cudaGetSymbolAddress((void**)&bp,  g_b);
    cudaGetSymbolAddress((void**)&cmp, g_colm);
    cudaGetSymbolAddress((void**)&csp, g_cols);

    int nsm = 148;
    cudaDeviceGetAttribute(&nsm, cudaDevAttrMultiProcessorCount, 0);
    int grid = 2 * nsm;
    if (grid > NBLKMAX) grid = NBLKMAX;

    const int smem_bytes = (3 * BDIM + 132) * (int)sizeof(float);
    cudaFuncSetAttribute(fused_iter_kernel,
                         cudaFuncAttributeMaxDynamicSharedMemorySize, smem_bytes);

    init_b_kernel<<<BDIM / 8, 256>>>(Y);

    dim3 ggrid(BDIM / 128, BDIM / 128);
    gemm_kernel<<<ggrid, 256>>>(X, Y);

    for (int it = 0; it < NITER; it++) {
        fused_iter_kernel<<<grid, 512, smem_bytes>>>(Mp, bp, cmp, csp);
        reduce_b_kernel<<<BDIM / 32, 512>>>(cmp, csp, bp, grid);
    }

    argmax_gather_kernel<<<BDIM / 8, 256>>>(Y, out);
}

// round 15
// speedup vs baseline: 1.3170x; 1.3170x over previous
#include <cuda_runtime.h>
#include <cstdint>
#include <cstddef>

#define BDIM 8192
#define CDIM 256
#define NITER 100
#define MAXROWS 64
#define PINROWS 1792   // 56 MB of each matrix kept L2-resident via __ldg
#define L2E 1.4426950408889634f
#define LN2 0.69314718055994531f

// Scratch: __device__ globals (no cudaMalloc allowed)
__device__ __align__(256) float g_M [(size_t)BDIM * BDIM];  // M[i][j]  = 2*x_i.y_j
__device__ __align__(256) float g_MT[(size_t)BDIM * BDIM];  // MT[j][i] = M[i][j]
__device__ __align__(256) float g_a[BDIM];
__device__ __align__(256) float g_b[BDIM];

__device__ __forceinline__ float ex2f(float x) {
    float y; asm("ex2.approx.f32 %0, %1;" : "=f"(y) : "f"(x)); return y;
}
__device__ __forceinline__ float lg2f(float x) {
    float y; asm("lg2.approx.f32 %0, %1;" : "=f"(y) : "f"(x)); return y;
}

// ---------------------------------------------------------------------------
// b init: b[j] = -||y_j||^2   (one warp per row, 8 rows per block)
// ---------------------------------------------------------------------------
__global__ __launch_bounds__(256) void init_b_kernel(const float* __restrict__ Y)
{
    int warp = threadIdx.x >> 5, lane = threadIdx.x & 31;
    int row = (blockIdx.x << 3) + warp;
    const float4* yr = (const float4*)Y + (size_t)row * (CDIM / 4);
    float4 v0 = yr[lane];
    float4 v1 = yr[lane + 32];
    float ss = 0.f;
    ss = fmaf(v0.x, v0.x, ss); ss = fmaf(v0.y, v0.y, ss);
    ss = fmaf(v0.z, v0.z, ss); ss = fmaf(v0.w, v0.w, ss);
    ss = fmaf(v1.x, v1.x, ss); ss = fmaf(v1.y, v1.y, ss);
    ss = fmaf(v1.z, v1.z, ss); ss = fmaf(v1.w, v1.w, ss);
    #pragma unroll
    for (int off = 16; off; off >>= 1)
        ss += __shfl_xor_sync(0xffffffffu, ss, off);
    if (lane == 0) g_b[row] = -ss;
}

// ---------------------------------------------------------------------------
// GEMM: M = 2 * X * Y^T, plus transposed copy MT.
// 128x128 tile, 256 threads, 8x8 per thread, k-step 16.
// ---------------------------------------------------------------------------
__global__ __launch_bounds__(256) void gemm_kernel(const float* __restrict__ X,
                                                   const float* __restrict__ Y)
{
    __shared__ float As[16][128];
    __shared__ float Bs[16][128];

    const int tid = threadIdx.x;
    const int tx = tid & 15;
    const int ty = tid >> 4;
    const int i0 = blockIdx.y << 7;
    const int j0 = blockIdx.x << 7;

    const float4* X4 = (const float4*)X;
    const float4* Y4 = (const float4*)Y;

    float acc[8][8];
    #pragma unroll
    for (int r = 0; r < 8; r++)
        #pragma unroll
        for (int c = 0; c < 8; c++) acc[r][c] = 0.f;

    for (int k0 = 0; k0 < CDIM; k0 += 16) {
        #pragma unroll
        for (int p = 0; p < 2; p++) {
            int f = tid + (p << 8);
            int r = f >> 2;
            int q = f & 3;
            float4 a = X4[(size_t)(i0 + r) * (CDIM / 4) + (k0 >> 2) + q];
            As[q * 4 + 0][r] = a.x; As[q * 4 + 1][r] = a.y;
            As[q * 4 + 2][r] = a.z; As[q * 4 + 3][r] = a.w;
            float4 b = Y4[(size_t)(j0 + r) * (CDIM / 4) + (k0 >> 2) + q];
            Bs[q * 4 + 0][r] = b.x; Bs[q * 4 + 1][r] = b.y;
            Bs[q * 4 + 2][r] = b.z; Bs[q * 4 + 3][r] = b.w;
        }
        __syncthreads();
        #pragma unroll
        for (int kk = 0; kk < 16; kk++) {
            float af[8], bf[8];
            *(float4*)&af[0] = *(const float4*)&As[kk][ty * 8];
            *(float4*)&af[4] = *(const float4*)&As[kk][ty * 8 + 4];
            *(float4*)&bf[0] = *(const float4*)&Bs[kk][tx * 8];
            *(float4*)&bf[4] = *(const float4*)&Bs[kk][tx * 8 + 4];
            #pragma unroll
            for (int r = 0; r < 8; r++)
                #pragma unroll
                for (int c = 0; c < 8; c++)
                    acc[r][c] = fmaf(af[r], bf[c], acc[r][c]);
        }
        __syncthreads();
    }

    #pragma unroll
    for (int r = 0; r < 8; r++) {
        int i = i0 + ty * 8 + r;
        float4 w0 = make_float4(2.f * acc[r][0], 2.f * acc[r][1],
                                2.f * acc[r][2], 2.f * acc[r][3]);
        float4 w1 = make_float4(2.f * acc[r][4], 2.f * acc[r][5],
                                2.f * acc[r][6], 2.f * acc[r][7]);
        float4* dst = (float4*)(g_M + (size_t)i * BDIM + j0 + tx * 8);
        dst[0] = w0; dst[1] = w1;
    }
    #pragma unroll
    for (int c = 0; c < 8; c++) {
        int j = j0 + tx * 8 + c;
        float4 t0 = make_float4(2.f * acc[0][c], 2.f * acc[1][c],
                                2.f * acc[2][c], 2.f * acc[3][c]);
        float4 t1 = make_float4(2.f * acc[4][c], 2.f * acc[5][c],
                                2.f * acc[6][c], 2.f * acc[7][c]);
        float4* dst = (float4*)(g_MT + (size_t)j * BDIM + i0 + ty * 8);
        dst[0] = t0; dst[1] = t1;
    }
}

// ---------------------------------------------------------------------------
// Dense LSE pass, single-wave balanced (R6 champion) + L2-pinned partition:
//   dst[row] = -logsumexp_j( Mmat[row][j] + src[j] )
// Rows < PINROWS are read with __ldg (default policy -> stay L2-resident,
// re-warmed every pass); the rest stream with __ldcs (evict-first, cannot
// displace the pinned set). 2 x 56 MB pinned (M + MT) fits the 126 MB L2.
// ---------------------------------------------------------------------------
__global__ __launch_bounds__(512, 2) void lse_pass_kernel(const float* __restrict__ Mmat,
                                                          const float* __restrict__ src,
                                                          float* __restrict__ dst)
{
    __shared__ float sb[BDIM];
    __shared__ float pm[MAXROWS * 8];
    __shared__ float ps[MAXROWS * 8];

    const int tid  = threadIdx.x;
    const int lane = tid & 31, warp = tid >> 5;
    const int nw   = blockDim.x >> 5;                 // 16 warps
    const int nblk = gridDim.x;
    const int r0   = (int)(((long long)BDIM * blockIdx.x) / nblk);
    const int r1   = (int)(((long long)BDIM * (blockIdx.x + 1)) / nblk);
    const int nrows = r1 - r0;
    const int nch   = nrows << 3;                     // 8 chunks per row

    // stage src
    float4* sb4 = (float4*)sb;
    const float4* s4 = (const float4*)src;
    #pragma unroll
    for (int k = 0; k < 4; k++) sb4[tid + 512 * k] = s4[tid + 512 * k];
    __syncthreads();

    for (int c = warp; c < nch; c += nw) {
        const int r = c >> 3;
        const int row = r0 + r;
        const int cb = (c & 7) << 8;                  // chunk base, float4 units
        const float4* m4 = (const float4*)(Mmat + ((size_t)row << 13)) + cb + lane;
        const float4* b4 = sb4 + cb + lane;

        float4 v[8];
        if (row < PINROWS) {
            #pragma unroll
            for (int u = 0; u < 8; u++) v[u] = __ldg(m4 + 32 * u);
        } else {
            #pragma unroll
            for (int u = 0; u < 8; u++) v[u] = __ldcs(m4 + 32 * u);
        }
        #pragma unroll
        for (int u = 0; u < 8; u++) {
            float4 bb = b4[32 * u];
            v[u].x += bb.x; v[u].y += bb.y;
            v[u].z += bb.z; v[u].w += bb.w;
        }
        float t[8];
        #pragma unroll
        for (int u = 0; u < 8; u++)
            t[u] = fmaxf(fmaxf(v[u].x, v[u].y), fmaxf(v[u].z, v[u].w));
        float lmax = fmaxf(fmaxf(fmaxf(t[0], t[1]), fmaxf(t[2], t[3])),
                           fmaxf(fmaxf(t[4], t[5]), fmaxf(t[6], t[7])));
        #pragma unroll
        for (int off = 16; off; off >>= 1)
            lmax = fmaxf(lmax, __shfl_xor_sync(0xffffffffu, lmax, off));

        const float mk = lmax * L2E;
        float s = 0.f;
        #pragma unroll
        for (int u = 0; u < 8; u++) {
            s += ex2f(fmaf(v[u].x, L2E, -mk));
            s += ex2f(fmaf(v[u].y, L2E, -mk));
            s += ex2f(fmaf(v[u].z, L2E, -mk));
            s += ex2f(fmaf(v[u].w, L2E, -mk));
        }
        #pragma unroll
        for (int off = 16; off; off >>= 1)
            s += __shfl_xor_sync(0xffffffffu, s, off);

        if (lane == 0) { pm[c] = lmax; ps[c] = s; }
    }
    __syncthreads();

    // per-row combine of 8 (m,s) pairs (deterministic fixed order)
    for (int r = tid; r < nrows; r += blockDim.x) {
        float m = pm[r * 8];
        #pragma unroll
        for (int k = 1; k < 8; k++) m = fmaxf(m, pm[r * 8 + k]);
        float s = 0.f;
        #pragma unroll
        for (int k = 0; k < 8; k++)
            s += ps[r * 8 + k] * ex2f((pm[r * 8 + k] - m) * L2E);
        dst[r0 + r] = -(m + lg2f(s) * LN2);
    }
}

// ---------------------------------------------------------------------------
// Final: out[i][:] = y[ argmax_j (M[i][j] + b[j]) ][:]
// ---------------------------------------------------------------------------
__global__ __launch_bounds__(256) void argmax_gather_kernel(const float* __restrict__ Y,
                                                            float* __restrict__ out)
{
    __shared__ float sb[BDIM];
    __shared__ float sval[8];
    __shared__ int   sidx[8];
    __shared__ int   sjbest;
    const int tid = threadIdx.x;
    const int lane = tid & 31, warp = tid >> 5;

    float4* sb4 = (float4*)sb;
    const float4* s4 = (const float4*)g_b;
    #pragma unroll
    for (int k = 0; k < 8; k++) sb4[tid + 256 * k] = s4[tid + 256 * k];
    __syncthreads();

    const int row0 = blockIdx.x << 3;
    for (int rr = 0; rr < 8; rr++) {
        const int row = row0 + rr;
        const float4* m4 = (const float4*)(g_M + (size_t)row * BDIM);

        float best = -3.0e38f;
        int bidx = 0x7fffffff;
        #pragma unroll
        for (int k = 0; k < 8; k++) {
            int f = tid + 256 * k;
            float4 m = __ldcs(m4 + f);
            float4 bb = sb4[f];
            float vx = m.x + bb.x, vy = m.y + bb.y, vz = m.z + bb.z, vw = m.w + bb.w;
            int j = f * 4;
            if (vx > best || (vx == best && j     < bidx)) { best = vx; bidx = j; }
            if (vy > best || (vy == best && j + 1 < bidx)) { best = vy; bidx = j + 1; }
            if (vz > best || (vz == best && j + 2 < bidx)) { best = vz; bidx = j + 2; }
            if (vw > best || (vw == best && j + 3 < bidx)) { best = vw; bidx = j + 3; }
        }
        #pragma unroll
        for (int off = 16; off; off >>= 1) {
            float ov = __shfl_xor_sync(0xffffffffu, best, off);
            int   oi = __shfl_xor_sync(0xffffffffu, bidx, off);
            if (ov > best || (ov == best && oi < bidx)) { best = ov; bidx = oi; }
        }
        if (lane == 0) { sval[warp] = best; sidx[warp] = bidx; }
        __syncthreads();
        if (tid == 0) {
            float bv = sval[0]; int bj = sidx[0];
            #pragma unroll
            for (int w = 1; w < 8; w++) {
                if (sval[w] > bv || (sval[w] == bv && sidx[w] < bj)) {
                    bv = sval[w]; bj = sidx[w];
                }
            }
            sjbest = bj;
        }
        __syncthreads();
        out[(size_t)row * CDIM + tid] = Y[(size_t)sjbest * CDIM + tid];
        __syncthreads();
    }
}

// ---------------------------------------------------------------------------
extern "C" void kernel_launch(void* const* d_in, const int* in_sizes, int n_in,
                              void* d_out, int out_size)
{
    const float* X = (const float*)d_in[0];
    const float* Y = (const float*)d_in[1];
    float* out = (float*)d_out;

    float *Mp, *MTp, *ap, *bp;
    cudaGetSymbolAddress((void**)&Mp,  g_M);
    cudaGetSymbolAddress((void**)&MTp, g_MT);
    cudaGetSymbolAddress((void**)&ap,  g_a);
    cudaGetSymbolAddress((void**)&bp,  g_b);

    int nsm = 148;
    cudaDeviceGetAttribute(&nsm, cudaDevAttrMultiProcessorCount, 0);
    int grid = 2 * nsm;
    if (grid < BDIM / MAXROWS) grid = BDIM / MAXROWS;   // keep nrows <= MAXROWS

    init_b_kernel<<<BDIM / 8, 256>>>(Y);

    dim3 ggrid(BDIM / 128, BDIM / 128);
    gemm_kernel<<<ggrid, 256>>>(X, Y);

    for (int it = 0; it < NITER; it++) {
        lse_pass_kernel<<<grid, 512>>>(Mp,  bp, ap);   // a = -lse_row(M + b)
        lse_pass_kernel<<<grid, 512>>>(MTp, ap, bp);   // b = -lse_col(M + a)
    }

    argmax_gather_kernel<<<BDIM / 8, 256>>>(Y, out);
}

// round 16
// speedup vs baseline: 1.3467x; 1.0226x over previous
#include <cuda_runtime.h>
#include <cstdint>
#include <cstddef>

#define BDIM 8192
#define CDIM 256
#define NITER 100
#define MAXROWS 64
#define L2E 1.4426950408889634f
#define LN2 0.69314718055994531f

// Scratch: __device__ globals (no cudaMalloc allowed)
__device__ __align__(256) float g_M [(size_t)BDIM * BDIM];  // M[i][j]  = 2*x_i.y_j
__device__ __align__(256) float g_MT[(size_t)BDIM * BDIM];  // MT[j][i] = M[i][j]
__device__ __align__(256) float g_a[BDIM];
__device__ __align__(256) float g_b[BDIM];

__device__ __forceinline__ float ex2f(float x) {
    float y; asm("ex2.approx.f32 %0, %1;" : "=f"(y) : "f"(x)); return y;
}
__device__ __forceinline__ float lg2f(float x) {
    float y; asm("lg2.approx.f32 %0, %1;" : "=f"(y) : "f"(x)); return y;
}

// ---------------------------------------------------------------------------
// b init: b[j] = -||y_j||^2   (one warp per row, 8 rows per block)
// ---------------------------------------------------------------------------
__global__ __launch_bounds__(256) void init_b_kernel(const float* __restrict__ Y)
{
    int warp = threadIdx.x >> 5, lane = threadIdx.x & 31;
    int row = (blockIdx.x << 3) + warp;
    const float4* yr = (const float4*)Y + (size_t)row * (CDIM / 4);
    float4 v0 = yr[lane];
    float4 v1 = yr[lane + 32];
    float ss = 0.f;
    ss = fmaf(v0.x, v0.x, ss); ss = fmaf(v0.y, v0.y, ss);
    ss = fmaf(v0.z, v0.z, ss); ss = fmaf(v0.w, v0.w, ss);
    ss = fmaf(v1.x, v1.x, ss); ss = fmaf(v1.y, v1.y, ss);
    ss = fmaf(v1.z, v1.z, ss); ss = fmaf(v1.w, v1.w, ss);
    #pragma unroll
    for (int off = 16; off; off >>= 1)
        ss += __shfl_xor_sync(0xffffffffu, ss, off);
    if (lane == 0) g_b[row] = -ss;
}

// ---------------------------------------------------------------------------
// GEMM: M = 2 * X * Y^T, plus transposed copy MT.
// 128x128 tile, 256 threads, 8x8 per thread, k-step 16.
// ---------------------------------------------------------------------------
__global__ __launch_bounds__(256) void gemm_kernel(const float* __restrict__ X,
                                                   const float* __restrict__ Y)
{
    __shared__ float As[16][128];
    __shared__ float Bs[16][128];

    const int tid = threadIdx.x;
    const int tx = tid & 15;
    const int ty = tid >> 4;
    const int i0 = blockIdx.y << 7;
    const int j0 = blockIdx.x << 7;

    const float4* X4 = (const float4*)X;
    const float4* Y4 = (const float4*)Y;

    float acc[8][8];
    #pragma unroll
    for (int r = 0; r < 8; r++)
        #pragma unroll
        for (int c = 0; c < 8; c++) acc[r][c] = 0.f;

    for (int k0 = 0; k0 < CDIM; k0 += 16) {
        #pragma unroll
        for (int p = 0; p < 2; p++) {
            int f = tid + (p << 8);
            int r = f >> 2;
            int q = f & 3;
            float4 a = X4[(size_t)(i0 + r) * (CDIM / 4) + (k0 >> 2) + q];
            As[q * 4 + 0][r] = a.x; As[q * 4 + 1][r] = a.y;
            As[q * 4 + 2][r] = a.z; As[q * 4 + 3][r] = a.w;
            float4 b = Y4[(size_t)(j0 + r) * (CDIM / 4) + (k0 >> 2) + q];
            Bs[q * 4 + 0][r] = b.x; Bs[q * 4 + 1][r] = b.y;
            Bs[q * 4 + 2][r] = b.z; Bs[q * 4 + 3][r] = b.w;
        }
        __syncthreads();
        #pragma unroll
        for (int kk = 0; kk < 16; kk++) {
            float af[8], bf[8];
            *(float4*)&af[0] = *(const float4*)&As[kk][ty * 8];
            *(float4*)&af[4] = *(const float4*)&As[kk][ty * 8 + 4];
            *(float4*)&bf[0] = *(const float4*)&Bs[kk][tx * 8];
            *(float4*)&bf[4] = *(const float4*)&Bs[kk][tx * 8 + 4];
            #pragma unroll
            for (int r = 0; r < 8; r++)
                #pragma unroll
                for (int c = 0; c < 8; c++)
                    acc[r][c] = fmaf(af[r], bf[c], acc[r][c]);
        }
        __syncthreads();
    }

    #pragma unroll
    for (int r = 0; r < 8; r++) {
        int i = i0 + ty * 8 + r;
        float4 w0 = make_float4(2.f * acc[r][0], 2.f * acc[r][1],
                                2.f * acc[r][2], 2.f * acc[r][3]);
        float4 w1 = make_float4(2.f * acc[r][4], 2.f * acc[r][5],
                                2.f * acc[r][6], 2.f * acc[r][7]);
        float4* dst = (float4*)(g_M + (size_t)i * BDIM + j0 + tx * 8);
        dst[0] = w0; dst[1] = w1;
    }
    #pragma unroll
    for (int c = 0; c < 8; c++) {
        int j = j0 + tx * 8 + c;
        float4 t0 = make_float4(2.f * acc[0][c], 2.f * acc[1][c],
                                2.f * acc[2][c], 2.f * acc[3][c]);
        float4 t1 = make_float4(2.f * acc[4][c], 2.f * acc[5][c],
                                2.f * acc[6][c], 2.f * acc[7][c]);
        float4* dst = (float4*)(g_MT + (size_t)j * BDIM + i0 + ty * 8);
        dst[0] = t0; dst[1] = t1;
    }
}

// ---------------------------------------------------------------------------
// Dense LSE pass, single-wave balanced (session champion):
//   dst[row] = -logsumexp_j( Mmat[row][j] + src[j] )
// Grid = 2*num_SMs blocks of 512 threads (2 resident/SM, exactly one wave).
// Block bi owns rows [8192*bi/nblk, 8192*(bi+1)/nblk). Work unit = 1024-col
// chunk; chunks striped statically over the 16 warps (deterministic).
// Each chunk -> exact local (max, sum) pair in registers; one barrier; tiny
// per-row 8-way combine. Measured: 43 us, 6.24 TB/s = 98.6% of the best
// HBM throughput observed on this chip.
// ---------------------------------------------------------------------------
__global__ __launch_bounds__(512, 2) void lse_pass_kernel(const float* __restrict__ Mmat,
                                                          const float* __restrict__ src,
                                                          float* __restrict__ dst)
{
    __shared__ float sb[BDIM];
    __shared__ float pm[MAXROWS * 8];
    __shared__ float ps[MAXROWS * 8];

    const int tid  = threadIdx.x;
    const int lane = tid & 31, warp = tid >> 5;
    const int nw   = blockDim.x >> 5;                 // 16 warps
    const int nblk = gridDim.x;
    const int r0   = (int)(((long long)BDIM * blockIdx.x) / nblk);
    const int r1   = (int)(((long long)BDIM * (blockIdx.x + 1)) / nblk);
    const int nrows = r1 - r0;
    const int nch   = nrows << 3;                     // 8 chunks per row

    // stage src
    float4* sb4 = (float4*)sb;
    const float4* s4 = (const float4*)src;
    #pragma unroll
    for (int k = 0; k < 4; k++) sb4[tid + 512 * k] = s4[tid + 512 * k];
    __syncthreads();

    for (int c = warp; c < nch; c += nw) {
        const int r = c >> 3;
        const int cb = (c & 7) << 8;                  // chunk base, float4 units
        const float4* m4 = (const float4*)(Mmat + ((size_t)(r0 + r) << 13)) + cb + lane;
        const float4* b4 = sb4 + cb + lane;

        float4 v[8];
        #pragma unroll
        for (int u = 0; u < 8; u++) {
            float4 mm = __ldcs(m4 + 32 * u);
            float4 bb = b4[32 * u];
            v[u].x = mm.x + bb.x; v[u].y = mm.y + bb.y;
            v[u].z = mm.z + bb.z; v[u].w = mm.w + bb.w;
        }
        float t[8];
        #pragma unroll
        for (int u = 0; u < 8; u++)
            t[u] = fmaxf(fmaxf(v[u].x, v[u].y), fmaxf(v[u].z, v[u].w));
        float lmax = fmaxf(fmaxf(fmaxf(t[0], t[1]), fmaxf(t[2], t[3])),
                           fmaxf(fmaxf(t[4], t[5]), fmaxf(t[6], t[7])));
        #pragma unroll
        for (int off = 16; off; off >>= 1)
            lmax = fmaxf(lmax, __shfl_xor_sync(0xffffffffu, lmax, off));

        const float mk = lmax * L2E;
        float s = 0.f;
        #pragma unroll
        for (int u = 0; u < 8; u++) {
            s += ex2f(fmaf(v[u].x, L2E, -mk));
            s += ex2f(fmaf(v[u].y, L2E, -mk));
            s += ex2f(fmaf(v[u].z, L2E, -mk));
            s += ex2f(fmaf(v[u].w, L2E, -mk));
        }
        #pragma unroll
        for (int off = 16; off; off >>= 1)
            s += __shfl_xor_sync(0xffffffffu, s, off);

        if (lane == 0) { pm[c] = lmax; ps[c] = s; }
    }
    __syncthreads();

    // per-row combine of 8 (m,s) pairs (deterministic fixed order)
    for (int r = tid; r < nrows; r += blockDim.x) {
        float m = pm[r * 8];
        #pragma unroll
        for (int k = 1; k < 8; k++) m = fmaxf(m, pm[r * 8 + k]);
        float s = 0.f;
        #pragma unroll
        for (int k = 0; k < 8; k++)
            s += ps[r * 8 + k] * ex2f((pm[r * 8 + k] - m) * L2E);
        dst[r0 + r] = -(m + lg2f(s) * LN2);
    }
}

// ---------------------------------------------------------------------------
// Final: out[i][:] = y[ argmax_j (M[i][j] + b[j]) ][:]
// ---------------------------------------------------------------------------
__global__ __launch_bounds__(256) void argmax_gather_kernel(const float* __restrict__ Y,
                                                            float* __restrict__ out)
{
    __shared__ float sb[BDIM];
    __shared__ float sval[8];
    __shared__ int   sidx[8];
    __shared__ int   sjbest;
    const int tid = threadIdx.x;
    const int lane = tid & 31, warp = tid >> 5;

    float4* sb4 = (float4*)sb;
    const float4* s4 = (const float4*)g_b;
    #pragma unroll
    for (int k = 0; k < 8; k++) sb4[tid + 256 * k] = s4[tid + 256 * k];
    __syncthreads();

    const int row0 = blockIdx.x << 3;
    for (int rr = 0; rr < 8; rr++) {
        const int row = row0 + rr;
        const float4* m4 = (const float4*)(g_M + (size_t)row * BDIM);

        float best = -3.0e38f;
        int bidx = 0x7fffffff;
        #pragma unroll
        for (int k = 0; k < 8; k++) {
            int f = tid + 256 * k;
            float4 m = __ldcs(m4 + f);
            float4 bb = sb4[f];
            float vx = m.x + bb.x, vy = m.y + bb.y, vz = m.z + bb.z, vw = m.w + bb.w;
            int j = f * 4;
            if (vx > best || (vx == best && j     < bidx)) { best = vx; bidx = j; }
            if (vy > best || (vy == best && j + 1 < bidx)) { best = vy; bidx = j + 1; }
            if (vz > best || (vz == best && j + 2 < bidx)) { best = vz; bidx = j + 2; }
            if (vw > best || (vw == best && j + 3 < bidx)) { best = vw; bidx = j + 3; }
        }
        #pragma unroll
        for (int off = 16; off; off >>= 1) {
            float ov = __shfl_xor_sync(0xffffffffu, best, off);
            int   oi = __shfl_xor_sync(0xffffffffu, bidx, off);
            if (ov > best || (ov == best && oi < bidx)) { best = ov; bidx = oi; }
        }
        if (lane == 0) { sval[warp] = best; sidx[warp] = bidx; }
        __syncthreads();
        if (tid == 0) {
            float bv = sval[0]; int bj = sidx[0];
            #pragma unroll
            for (int w = 1; w < 8; w++) {
                if (sval[w] > bv || (sval[w] == bv && sidx[w] < bj)) {
                    bv = sval[w]; bj = sidx[w];
                }
            }
            sjbest = bj;
        }
        __syncthreads();
        out[(size_t)row * CDIM + tid] = Y[(size_t)sjbest * CDIM + tid];
        __syncthreads();
    }
}

// ---------------------------------------------------------------------------
extern "C" void kernel_launch(void* const* d_in, const int* in_sizes, int n_in,
                              void* d_out, int out_size)
{
    const float* X = (const float*)d_in[0];
    const float* Y = (const float*)d_in[1];
    float* out = (float*)d_out;

    float *Mp, *MTp, *ap, *bp;
    cudaGetSymbolAddress((void**)&Mp,  g_M);
    cudaGetSymbolAddress((void**)&MTp, g_MT);
    cudaGetSymbolAddress((void**)&ap,  g_a);
    cudaGetSymbolAddress((void**)&bp,  g_b);

    int nsm = 148;
    cudaDeviceGetAttribute(&nsm, cudaDevAttrMultiProcessorCount, 0);
    int grid = 2 * nsm;
    if (grid < BDIM / MAXROWS) grid = BDIM / MAXROWS;   // keep nrows <= MAXROWS

    init_b_kernel<<<BDIM / 8, 256>>>(Y);

    dim3 ggrid(BDIM / 128, BDIM / 128);
    gemm_kernel<<<ggrid, 256>>>(X, Y);

    for (int it = 0; it < NITER; it++) {
        lse_pass_kernel<<<grid, 512>>>(Mp,  bp, ap);   // a = -lse_row(M + b)
        lse_pass_kernel<<<grid, 512>>>(MTp, ap, bp);   // b = -lse_col(M + a)
    }

    argmax_gather_kernel<<<BDIM / 8, 256>>>(Y, out);
}

// round 17
// speedup vs baseline: 1.7170x; 1.2750x over previous
#include <cuda_runtime.h>
#include <cstdint>
#include <cstddef>

#define BDIM 8192
#define CDIM 256
#define NITER 100
#define NBLKMAX 1024
#define NQUAD (BDIM / 4)
#define NSEG 16
#define SHIFT 60.0f
#define L2E 1.4426950408889634f
#define LN2 0.69314718055994531f

// Scratch: __device__ globals (no cudaMalloc allowed)
__device__ __align__(256) float g_M [(size_t)BDIM * BDIM];      // M[i][j] = 2*x_i.y_j
__device__ __align__(256) float g_b[BDIM];
__device__ __align__(256) float g_colp[(size_t)NBLKMAX * BDIM]; // per-block col sum partials

__device__ __forceinline__ float ex2f(float x) {
    float y; asm("ex2.approx.f32 %0, %1;" : "=f"(y) : "f"(x)); return y;
}
__device__ __forceinline__ float lg2f(float x) {
    float y; asm("lg2.approx.f32 %0, %1;" : "=f"(y) : "f"(x)); return y;
}

// ---------------------------------------------------------------------------
// b init: b[j] = -||y_j||^2   (one warp per row, 8 rows per block)
// ---------------------------------------------------------------------------
__global__ __launch_bounds__(256) void init_b_kernel(const float* __restrict__ Y)
{
    int warp = threadIdx.x >> 5, lane = threadIdx.x & 31;
    int row = (blockIdx.x << 3) + warp;
    const float4* yr = (const float4*)Y + (size_t)row * (CDIM / 4);
    float4 v0 = yr[lane];
    float4 v1 = yr[lane + 32];
    float ss = 0.f;
    ss = fmaf(v0.x, v0.x, ss); ss = fmaf(v0.y, v0.y, ss);
    ss = fmaf(v0.z, v0.z, ss); ss = fmaf(v0.w, v0.w, ss);
    ss = fmaf(v1.x, v1.x, ss); ss = fmaf(v1.y, v1.y, ss);
    ss = fmaf(v1.z, v1.z, ss); ss = fmaf(v1.w, v1.w, ss);
    #pragma unroll
    for (int off = 16; off; off >>= 1)
        ss += __shfl_xor_sync(0xffffffffu, ss, off);
    if (lane == 0) g_b[row] = -ss;
}

// ---------------------------------------------------------------------------
// GEMM: M = 2 * X * Y^T (row-major only; no transpose needed anymore).
// ---------------------------------------------------------------------------
__global__ __launch_bounds__(256) void gemm_kernel(const float* __restrict__ X,
                                                   const float* __restrict__ Y)
{
    __shared__ float As[16][128];
    __shared__ float Bs[16][128];

    const int tid = threadIdx.x;
    const int tx = tid & 15;
    const int ty = tid >> 4;
    const int i0 = blockIdx.y << 7;
    const int j0 = blockIdx.x << 7;

    const float4* X4 = (const float4*)X;
    const float4* Y4 = (const float4*)Y;

    float acc[8][8];
    #pragma unroll
    for (int r = 0; r < 8; r++)
        #pragma unroll
        for (int c = 0; c < 8; c++) acc[r][c] = 0.f;

    for (int k0 = 0; k0 < CDIM; k0 += 16) {
        #pragma unroll
        for (int p = 0; p < 2; p++) {
            int f = tid + (p << 8);
            int r = f >> 2;
            int q = f & 3;
            float4 a = X4[(size_t)(i0 + r) * (CDIM / 4) + (k0 >> 2) + q];
            As[q * 4 + 0][r] = a.x; As[q * 4 + 1][r] = a.y;
            As[q * 4 + 2][r] = a.z; As[q * 4 + 3][r] = a.w;
            float4 b = Y4[(size_t)(j0 + r) * (CDIM / 4) + (k0 >> 2) + q];
            Bs[q * 4 + 0][r] = b.x; Bs[q * 4 + 1][r] = b.y;
            Bs[q * 4 + 2][r] = b.z; Bs[q * 4 + 3][r] = b.w;
        }
        __syncthreads();
        #pragma unroll
        for (int kk = 0; kk < 16; kk++) {
            float af[8], bf[8];
            *(float4*)&af[0] = *(const float4*)&As[kk][ty * 8];
            *(float4*)&af[4] = *(const float4*)&As[kk][ty * 8 + 4];
            *(float4*)&bf[0] = *(const float4*)&Bs[kk][tx * 8];
            *(float4*)&bf[4] = *(const float4*)&Bs[kk][tx * 8 + 4];
            #pragma unroll
            for (int r = 0; r < 8; r++)
                #pragma unroll
                for (int c = 0; c < 8; c++)
                    acc[r][c] = fmaf(af[r], bf[c], acc[r][c]);
        }
        __syncthreads();
    }

    #pragma unroll
    for (int r = 0; r < 8; r++) {
        int i = i0 + ty * 8 + r;
        float4 w0 = make_float4(2.f * acc[r][0], 2.f * acc[r][1],
                                2.f * acc[r][2], 2.f * acc[r][3]);
        float4 w1 = make_float4(2.f * acc[r][4], 2.f * acc[r][5],
                                2.f * acc[r][6], 2.f * acc[r][7]);
        float4* dst = (float4*)(g_M + (size_t)i * BDIM + j0 + tx * 8);
        dst[0] = w0; dst[1] = w1;
    }
}

// ---------------------------------------------------------------------------
// Fused Sinkhorn iteration, ONE sweep of M per iteration:
//   a_i = -lse_j(M_ij + b_j)   (Phase A: DRAM stream, __ldg keeps lines in L2)
//   col partials: cs_j += exp(c_ij + 60), c_ij = M_ij + b_j + a_i <= 0
//                              (Phase B: L2 re-read, __ldcs, branch-free)
//   b_new_j = b_old_j - (log(sum_blocks cs) - 60)   [reduce_b_kernel]
// Quad-aligned row ranges: all warps follow identical control flow.
// Warp w owns column stripe [512w, 512w+512); col sums stripe-private.
// ---------------------------------------------------------------------------
__global__ __launch_bounds__(512, 2) void fused_iter_kernel(const float* __restrict__ Mmat,
                                                            const float* __restrict__ bsrc,
                                                            float* __restrict__ colp)
{
    extern __shared__ float dsm[];
    float* sb = dsm;               // 8192: staged b
    float* cs = dsm + 8192;        // 8192: per-col shifted-exp sums
    float* pm = dsm + 16384;       // 64: stripe maxes (4 rows x 16)
    float* ps = pm + 64;           // 64: stripe sums
    float* sa = ps + 64;           // 4: a[0..3]

    const int tid = threadIdx.x;
    const int lane = tid & 31, warp = tid >> 5;
    const int nblk = gridDim.x;
    const int q0 = (int)(((long long)NQUAD * blockIdx.x) / nblk);
    const int q1 = (int)(((long long)NQUAD * (blockIdx.x + 1)) / nblk);
    const int r0 = q0 << 2, r1 = q1 << 2;

    // stage b
    float4* sb4 = (float4*)sb;
    const float4* s4 = (const float4*)bsrc;
    #pragma unroll
    for (int k = 0; k < 4; k++) sb4[tid + 512 * k] = s4[tid + 512 * k];

    // zero stripe-private col sums
    float4* cs4 = (float4*)cs;
    const int sbase = warp * 128 + lane;      // float4 index within row
    #pragma unroll
    for (int u = 0; u < 4; u++)
        cs4[sbase + 32 * u] = make_float4(0.f, 0.f, 0.f, 0.f);
    __syncthreads();

    const float4* Mb = (const float4*)Mmat;

    for (int r = r0; r < r1; r += 4) {
        // ---- Phase A: row (max,sum), streaming from DRAM ----
        #pragma unroll
        for (int b = 0; b < 4; b++) {
            float4 v[4];
            #pragma unroll
            for (int u = 0; u < 4; u++)
                v[u] = __ldg(Mb + ((size_t)(r + b) << 11) + sbase + 32 * u);
            #pragma unroll
            for (int u = 0; u < 4; u++) {
                float4 bb = sb4[sbase + 32 * u];
                v[u].x += bb.x; v[u].y += bb.y;
                v[u].z += bb.z; v[u].w += bb.w;
            }
            float m = -3.0e38f;
            #pragma unroll
            for (int u = 0; u < 4; u++)
                m = fmaxf(m, fmaxf(fmaxf(v[u].x, v[u].y), fmaxf(v[u].z, v[u].w)));
            #pragma unroll
            for (int off = 16; off; off >>= 1)
                m = fmaxf(m, __shfl_xor_sync(0xffffffffu, m, off));
            const float mk = m * L2E;
            float s = 0.f;
            #pragma unroll
            for (int u = 0; u < 4; u++) {
                s += ex2f(fmaf(v[u].x, L2E, -mk));
                s += ex2f(fmaf(v[u].y, L2E, -mk));
                s += ex2f(fmaf(v[u].z, L2E, -mk));
                s += ex2f(fmaf(v[u].w, L2E, -mk));
            }
            #pragma unroll
            for (int off = 16; off; off >>= 1)
                s += __shfl_xor_sync(0xffffffffu, s, off);
            if (lane == 0) { pm[b * 16 + warp] = m; ps[b * 16 + warp] = s; }
        }
        __syncthreads();

        // combine (warps 0-1, 16 lanes/row, no divergence: always 4 rows)
        if (warp < 2) {
            const int row_b = warp * 2 + (lane >> 4);
            const int stripe = lane & 15;
            float m = pm[row_b * 16 + stripe];
            float s = ps[row_b * 16 + stripe];
            float mm = m;
            #pragma unroll
            for (int off = 1; off <= 8; off <<= 1)
                mm = fmaxf(mm, __shfl_xor_sync(0xffffffffu, mm, off));
            float t = s * ex2f((m - mm) * L2E);
            #pragma unroll
            for (int off = 1; off <= 8; off <<= 1)
                t += __shfl_xor_sync(0xffffffffu, t, off);
            if ((lane & 15) == 0) sa[row_b] = -(mm + lg2f(t) * LN2);
        }
        __syncthreads();

        // ---- Phase B: L2 re-read, branch-free shifted-exp col accumulate ----
        float4 csv[4];
        #pragma unroll
        for (int u = 0; u < 4; u++) csv[u] = cs4[sbase + 32 * u];
        #pragma unroll
        for (int b = 0; b < 4; b++) {
            const float abk = (sa[b] + SHIFT) * L2E;   // (a + 60) in log2 units
            #pragma unroll
            for (int u = 0; u < 4; u++) {
                float4 mmv = __ldcs(Mb + ((size_t)(r + b) << 11) + sbase + 32 * u);
                float4 bb = sb4[sbase + 32 * u];
                csv[u].x += ex2f(fmaf(mmv.x + bb.x, L2E, abk));
                csv[u].y += ex2f(fmaf(mmv.y + bb.y, L2E, abk));
                csv[u].z += ex2f(fmaf(mmv.z + bb.z, L2E, abk));
                csv[u].w += ex2f(fmaf(mmv.w + bb.w, L2E, abk));
            }
        }
        #pragma unroll
        for (int u = 0; u < 4; u++) cs4[sbase + 32 * u] = csv[u];
        // next batch's Phase-A __syncthreads guards pm/ps/sa reuse
    }
    __syncthreads();

    // write block partials (coalesced)
    float* cso = colp + (size_t)blockIdx.x * BDIM;
    #pragma unroll
    for (int k = 0; k < 16; k++) cso[tid + 512 * k] = cs[tid + 512 * k];
}

// ---------------------------------------------------------------------------
// Plain-sum combine: b[j] -= log(sum_k colp[k][j]) - SHIFT.
// 16 segments x 32 lanes, fixed order -> deterministic.
// ---------------------------------------------------------------------------
__global__ __launch_bounds__(512) void reduce_b_kernel(const float* __restrict__ colp,
                                                       float* __restrict__ b, int nblk)
{
    __shared__ float sm_s[NSEG][32];
    const int lane32 = threadIdx.x & 31;
    const int seg = threadIdx.x >> 5;
    const int j = blockIdx.x * 32 + lane32;
    const int k0 = seg * nblk / NSEG;
    const int k1 = (seg + 1) * nblk / NSEG;

    float s0 = 0.f, s1 = 0.f;
    int k = k0;
    for (; k + 1 < k1; k += 2) {
        s0 += colp[(size_t)k * BDIM + j];
        s1 += colp[(size_t)(k + 1) * BDIM + j];
    }
    if (k < k1) s0 += colp[(size_t)k * BDIM + j];
    sm_s[seg][lane32] = s0 + s1;
    __syncthreads();

    if (threadIdx.x < 32) {
        float tot = sm_s[0][lane32];
        #pragma unroll
        for (int q = 1; q < NSEG; q++) tot += sm_s[q][lane32];
        b[j] = b[j] - (lg2f(tot) * LN2 - SHIFT);
    }
}

// ---------------------------------------------------------------------------
// Final: out[i][:] = y[ argmax_j (M[i][j] + b[j]) ][:]
// ---------------------------------------------------------------------------
__global__ __launch_bounds__(256) void argmax_gather_kernel(const float* __restrict__ Y,
                                                            float* __restrict__ out)
{
    __shared__ float sb[BDIM];
    __shared__ float sval[8];
    __shared__ int   sidx[8];
    __shared__ int   sjbest;
    const int tid = threadIdx.x;
    const int lane = tid & 31, warp = tid >> 5;

    float4* sb4 = (float4*)sb;
    const float4* s4 = (const float4*)g_b;
    #pragma unroll
    for (int k = 0; k < 8; k++) sb4[tid + 256 * k] = s4[tid + 256 * k];
    __syncthreads();

    const int row0 = blockIdx.x << 3;
    for (int rr = 0; rr < 8; rr++) {
        const int row = row0 + rr;
        const float4* m4 = (const float4*)(g_M + (size_t)row * BDIM);

        float best = -3.0e38f;
        int bidx = 0x7fffffff;
        #pragma unroll
        for (int k = 0; k < 8; k++) {
            int f = tid + 256 * k;
            float4 m = __ldcs(m4 + f);
            float4 bb = sb4[f];
            float vx = m.x + bb.x, vy = m.y + bb.y, vz = m.z + bb.z, vw = m.w + bb.w;
            int j = f * 4;
            if (vx > best || (vx == best && j     < bidx)) { best = vx; bidx = j; }
            if (vy > best || (vy == best && j + 1 < bidx)) { best = vy; bidx = j + 1; }
            if (vz > best || (vz == best && j + 2 < bidx)) { best = vz; bidx = j + 2; }
            if (vw > best || (vw == best && j + 3 < bidx)) { best = vw; bidx = j + 3; }
        }
        #pragma unroll
        for (int off = 16; off; off >>= 1) {
            float ov = __shfl_xor_sync(0xffffffffu, best, off);
            int   oi = __shfl_xor_sync(0xffffffffu, bidx, off);
            if (ov > best || (ov == best && oi < bidx)) { best = ov; bidx = oi; }
        }
        if (lane == 0) { sval[warp] = best; sidx[warp] = bidx; }
        __syncthreads();
        if (tid == 0) {
            float bv = sval[0]; int bj = sidx[0];
            #pragma unroll
            for (int w = 1; w < 8; w++) {
                if (sval[w] > bv || (sval[w] == bv && sidx[w] < bj)) {
                    bv = sval[w]; bj = sidx[w];
                }
            }
            sjbest = bj;
        }
        __syncthreads();
        out[(size_t)row * CDIM + tid] = Y[(size_t)sjbest * CDIM + tid];
        __syncthreads();
    }
}

// ---------------------------------------------------------------------------
extern "C" void kernel_launch(void* const* d_in, const int* in_sizes, int n_in,
                              void* d_out, int out_size)
{
    const float* X = (const float*)d_in[0];
    const float* Y = (const float*)d_in[1];
    float* out = (float*)d_out;

    float *Mp, *bp, *cpp;
    cudaGetSymbolAddress((void**)&Mp,  g_M);
    cudaGetSymbolAddress((void**)&bp,  g_b);
    cudaGetSymbolAddress((void**)&cpp, g_colp);

    int nsm = 148;
    cudaDeviceGetAttribute(&nsm, cudaDevAttrMultiProcessorCount, 0);
    int grid = 2 * nsm;
    if (grid > NBLKMAX) grid = NBLKMAX;

    const int smem_bytes = (2 * BDIM + 132) * (int)sizeof(float);
    cudaFuncSetAttribute(fused_iter_kernel,
                         cudaFuncAttributeMaxDynamicSharedMemorySize, smem_bytes);

    init_b_kernel<<<BDIM / 8, 256>>>(Y);

    dim3 ggrid(BDIM / 128, BDIM / 128);
    gemm_kernel<<<ggrid, 256>>>(X, Y);

    for (int it = 0; it < NITER; it++) {
        fused_iter_kernel<<<grid, 512, smem_bytes>>>(Mp, bp, cpp);
        reduce_b_kernel<<<BDIM / 32, 512>>>(cpp, bp, grid);
    }

    argmax_gather_kernel<<<BDIM / 8, 256>>>(Y, out);
}